// round 6
// baseline (speedup 1.0000x reference)
#include <cuda_runtime.h>
#include <math.h>

#define R_HASH 0.2f
#define EPSF   1e-12f
#define BATCH  4096

// scratch (device globals: sanctioned scratch mechanism)
__device__ float g_h1[BATCH * 16 * 16 * 16];
__device__ float g_h2[BATCH * 20 * 8 * 8];
__device__ float g_h3[BATCH * 20 * 4 * 4];
__device__ int   g_qh[3 * BATCH];
__device__ int   g_kh[96];
__device__ float g_aux[48];
__device__ float g_w1p[16 * 3 * 28];    // padded weights, stride 28 (7xfloat4)
__device__ float g_w2p[20 * 16 * 28];
__device__ float g_w3p[20 * 20 * 28];

// ---------------------------------------------------------------------------
// Pad weights to 28-stride (16B-aligned rows for float4 loads)
// ---------------------------------------------------------------------------
__global__ void prep_wpad(const float* __restrict__ W1,
                          const float* __restrict__ W2,
                          const float* __restrict__ W3)
{
    int t = blockIdx.x * blockDim.x + threadIdx.x;
    int stride = gridDim.x * blockDim.x;
    for (int i = t; i < 48 * 28; i += stride) {
        int f = i / 28, k = i % 28;
        g_w1p[i] = (k < 25) ? W1[f * 25 + k] : 0.f;
    }
    for (int i = t; i < 320 * 28; i += stride) {
        int f = i / 28, k = i % 28;
        g_w2p[i] = (k < 25) ? W2[f * 25 + k] : 0.f;
    }
    for (int i = t; i < 400 * 28; i += stride) {
        int f = i / 28, k = i % 28;
        g_w3p[i] = (k < 25) ? W3[f * 25 + k] : 0.f;
    }
}

// ---------------------------------------------------------------------------
// Filter hashes (one warp per layer)
// ---------------------------------------------------------------------------
__device__ __forceinline__ void kh_layer(const float* W, const float* a,
                                         const float* c, int Cout, int d,
                                         int* kh_out, int t)
{
    float nrm = 0.f;
    if (t < Cout) {
        for (int j = 0; j < d; j++) { float v = W[t * d + j]; nrm += v * v; }
        nrm = sqrtf(nrm);
    }
    float mx = nrm;
    #pragma unroll
    for (int off = 16; off; off >>= 1)
        mx = fmaxf(mx, __shfl_xor_sync(0xffffffffu, mx, off));
    float scale = 1.f / (mx + EPSF);
    if (t < Cout) {
        float dot = 0.f, ss = 0.f;
        for (int j = 0; j < d; j++) {
            float v = W[t * d + j] * scale;
            dot += v * a[j];
            ss  += v * v;
        }
        float n = sqrtf(ss);
        float p = n;
        #pragma unroll
        for (int m = 0; m < 5; m++) { p = p * p; dot += p * a[d + m]; }
        dot += c[0];
        long long f = (long long)floorf(dot / R_HASH);
        kh_out[t] = (int)(((f % 2) + 2) % 2);
    }
}

__global__ void kh_kernel(const float* W1, const float* a1, const float* c1,
                          const float* W2, const float* a2, const float* c2,
                          const float* W3, const float* a3, const float* c3)
{
    int warp = threadIdx.x >> 5, t = threadIdx.x & 31;
    if (warp == 0) kh_layer(W1, a1, c1, 16, 3 * 25,  g_kh + 0,  t);
    if (warp == 1) kh_layer(W2, a2, c2, 20, 16 * 25, g_kh + 32, t);
    if (warp == 2) kh_layer(W3, a3, c3, 20, 20 * 25, g_kh + 64, t);
    if (warp == 3 && t < 16) {
        float s = 0.f; for (int j = 0; j < 25; j++) s += a2[t * 25 + j];
        g_aux[t] = s;
    }
    if (warp == 4 && t < 20) {
        float s = 0.f; for (int j = 0; j < 25; j++) s += a3[t * 25 + j];
        g_aux[16 + t] = s;
    }
    if (warp == 5) {
        if (t < 3) {
            float s = 0.f; for (int j = 0; j < 25; j++) s += a1[t * 25 + j];
            g_aux[38 + t] = s;
        }
        if (t == 3) { float s = 0.f; for (int m = 0; m < 5; m++) s += a2[400 + m]; g_aux[36] = s; }
        if (t == 4) { float s = 0.f; for (int m = 0; m < 5; m++) s += a3[500 + m]; g_aux[37] = s; }
        if (t == 5) { float s = 0.f; for (int m = 0; m < 5; m++) s += a1[75 + m];  g_aux[41] = s; }
    }
}

// ---------------------------------------------------------------------------
// Layer-1 query hash: one warp per sample
// ---------------------------------------------------------------------------
__global__ __launch_bounds__(256)
void qh1_kernel(const float* __restrict__ x, const float* __restrict__ c1,
                int* __restrict__ qh_out)
{
    int warp = threadIdx.x >> 5, lane = threadIdx.x & 31;
    int b = blockIdx.x * 8 + warp;
    const float4* xb = (const float4*)(x + (size_t)b * 3072);
    float s[3];
    #pragma unroll
    for (int c = 0; c < 3; c++) {
        float p = 0.f;
        #pragma unroll
        for (int i = lane; i < 256; i += 32) {
            float4 v = xb[c * 256 + i];
            p += (v.x + v.y) + (v.z + v.w);
        }
        #pragma unroll
        for (int off = 16; off; off >>= 1)
            p += __shfl_xor_sync(0xffffffffu, p, off);
        s[c] = p;
    }
    if (lane == 0) {
        float dot = 0.f, ss = 0.f;
        #pragma unroll
        for (int c = 0; c < 3; c++) {
            float cm = s[c] * (1.f / 1024.f);
            dot += cm * g_aux[38 + c];
            ss  += cm * cm;
        }
        float v = dot / (sqrtf(25.f * ss) + EPSF) + 0.5f * g_aux[41] + c1[0];
        long long f = (long long)floorf(v / R_HASH);
        qh_out[b] = (int)(((f % 2) + 2) % 2);
    }
}

// ---------------------------------------------------------------------------
// Fused conv5x5(pad2)+bias+relu+mask+maxpool2.
// Compacted active-channel x tiles in smem; padded weights via float4 __ldg
// with software prefetch (double buffer) to hide load latency.
// ---------------------------------------------------------------------------
template <int CIN, int COUT, int H, int W, int WPAD, int SPB, int T, int MINB, bool EPI>
__global__ __launch_bounds__(T, MINB)
void conv_fused(const float* __restrict__ in, float* __restrict__ out,
                const float* __restrict__ wpad, const float* __restrict__ bias,
                const int* __restrict__ kh, const int* __restrict__ qh,
                const int* __restrict__ kh_prev, const int* __restrict__ qh_prev,
                const float* __restrict__ asum_next,
                const float* __restrict__ tail_next,
                const float* __restrict__ c_next, int* __restrict__ qh_next)
{
    constexpr int HP = H + 4;
    constexpr int PH = H / 2, PW = W / 2, PX2 = PW / 2;
    constexpr int PP = PH * PX2;
    constexpr int SEG = (PP < 32) ? PP : 32;
    constexpr int CHW = HP * WPAD;

    extern __shared__ float sm[];
    float* sx  = sm;                              // SPB*CIN*CHW (worst case)
    float* scm = sx + SPB * CIN * CHW;            // SPB*COUT
    int* nact  = (int*)(scm + SPB * COUT);        // SPB
    int* soff  = nact + SPB;                      // SPB+1
    int* actco = soff + SPB + 1;                  // SPB*COUT
    int* nci   = actco + SPB * COUT;              // SPB
    int* actci = nci + SPB;                       // SPB*CIN
    int* sxoff = actci + SPB * CIN;               // SPB+1

    const int b0 = blockIdx.x * SPB;
    const int t  = threadIdx.x;

    if (t < SPB) {
        int s = t, n = 0, qv = qh[b0 + s];
        for (int co = 0; co < COUT; co++)
            if (kh[co] == qv) actco[s * COUT + n++] = co;
        nact[s] = n;
    } else if (t >= 32 && t < 32 + SPB) {
        int s = t - 32, n = 0;
        if (kh_prev) {
            int qv = qh_prev[b0 + s];
            for (int c = 0; c < CIN; c++)
                if (kh_prev[c] == qv) actci[s * CIN + n++] = c;
        } else {
            for (int c = 0; c < CIN; c++) actci[s * CIN + n++] = c;
        }
        nci[s] = n;
    }
    if (EPI) for (int i = t; i < SPB * COUT; i += T) scm[i] = 0.f;
    __syncthreads();
    if (t == 0) {
        int o = 0, xo = 0;
        for (int s = 0; s < SPB; s++) {
            soff[s] = o;  o  += nact[s] * PP;
            sxoff[s] = xo; xo += nci[s];
        }
        soff[SPB] = o; sxoff[SPB] = xo;
    }
    __syncthreads();

    // stage compacted active-channel input tiles
    const int total_ch = sxoff[SPB];
    for (int i = t; i < total_ch * CHW; i += T) {
        int pos = i % CHW, ch = i / CHW;
        int s = 0;
        #pragma unroll
        for (int ss = 0; ss < SPB - 1; ss++)
            if (ch >= sxoff[ss + 1]) s = ss + 1;
        int c = actci[s * CIN + (ch - sxoff[s])];
        int py = pos / WPAD, px = pos % WPAD;
        int y = py - 2, x = px - 2;
        float v = 0.f;
        if ((unsigned)y < (unsigned)H && (unsigned)x < (unsigned)W)
            v = in[((size_t)(b0 + s) * CIN + c) * (H * W) + y * W + x];
        sx[i] = v;
    }
    __syncthreads();
    const int total = soff[SPB];

    for (int item = t;; item += T) {
        if (!__ballot_sync(0xffffffffu, item < total)) break;
        float val = 0.f;
        int s = 0, co = 0;
        if (item < total) {
            #pragma unroll
            for (int ss = 0; ss < SPB - 1; ss++)
                if (item >= soff[ss + 1]) s = ss + 1;
            int local = item - soff[s];
            co = actco[s * COUT + local / PP];
            int rr = local % PP;
            int py = rr / PX2, px2 = rr % PX2;

            float acc[2][4] = {};
            const float* xb = sx + (size_t)sxoff[s] * CHW + (2 * py) * WPAD + 4 * px2;
            const int n_ci = nci[s];
            const int* ci = actci + s * CIN;
            const float* wb_ = wpad + (size_t)co * CIN * 28;

            float4 cur[7];
            {
                int c0 = (n_ci > 0) ? ci[0] : 0;
                const float4* wr = (const float4*)(wb_ + c0 * 28);
                #pragma unroll
                for (int k = 0; k < 7; k++) cur[k] = __ldg(wr + k);
            }
            for (int j = 0; j < n_ci; j++) {
                float4 nxt[7];
                if (j + 1 < n_ci) {
                    const float4* wn = (const float4*)(wb_ + ci[j + 1] * 28);
                    #pragma unroll
                    for (int k = 0; k < 7; k++) nxt[k] = __ldg(wn + k);
                } else {
                    #pragma unroll
                    for (int k = 0; k < 7; k++) nxt[k] = cur[k];
                }
                float w[25];
                #pragma unroll
                for (int k = 0; k < 6; k++) {
                    w[4 * k + 0] = cur[k].x; w[4 * k + 1] = cur[k].y;
                    w[4 * k + 2] = cur[k].z; w[4 * k + 3] = cur[k].w;
                }
                w[24] = cur[6].x;

                const float* xs = xb + j * CHW;
                #pragma unroll
                for (int rw = 0; rw < 6; rw++) {
                    float4 x0 = *(const float4*)(xs + rw * WPAD);
                    float4 x1 = *(const float4*)(xs + rw * WPAD + 4);
                    float xr[8] = {x0.x, x0.y, x0.z, x0.w, x1.x, x1.y, x1.z, x1.w};
                    if (rw < 5) {
                        #pragma unroll
                        for (int kx = 0; kx < 5; kx++) {
                            float wa = w[rw * 5 + kx];
                            acc[0][0] += xr[kx + 0] * wa;
                            acc[0][1] += xr[kx + 1] * wa;
                            acc[0][2] += xr[kx + 2] * wa;
                            acc[0][3] += xr[kx + 3] * wa;
                        }
                    }
                    if (rw > 0) {
                        #pragma unroll
                        for (int kx = 0; kx < 5; kx++) {
                            float wb = w[(rw - 1) * 5 + kx];
                            acc[1][0] += xr[kx + 0] * wb;
                            acc[1][1] += xr[kx + 1] * wb;
                            acc[1][2] += xr[kx + 2] * wb;
                            acc[1][3] += xr[kx + 3] * wb;
                        }
                    }
                }
                #pragma unroll
                for (int k = 0; k < 7; k++) cur[k] = nxt[k];
            }
            float bv = __ldg(bias + co);
            float v00 = fmaxf(acc[0][0] + bv, 0.f), v01 = fmaxf(acc[0][1] + bv, 0.f);
            float v02 = fmaxf(acc[0][2] + bv, 0.f), v03 = fmaxf(acc[0][3] + bv, 0.f);
            float v10 = fmaxf(acc[1][0] + bv, 0.f), v11 = fmaxf(acc[1][1] + bv, 0.f);
            float v12 = fmaxf(acc[1][2] + bv, 0.f), v13 = fmaxf(acc[1][3] + bv, 0.f);
            float o0 = fmaxf(fmaxf(v00, v01), fmaxf(v10, v11));
            float o1 = fmaxf(fmaxf(v02, v03), fmaxf(v12, v13));
            float2* op = (float2*)&out[(((size_t)(b0 + s) * COUT + co) * PH + py) * PW + px2 * 2];
            *op = make_float2(o0, o1);
            val = o0 + o1;
        }
        if (EPI) {
            #pragma unroll
            for (int off = SEG / 2; off; off >>= 1)
                val += __shfl_xor_sync(0xffffffffu, val, off);
            if ((t & (SEG - 1)) == 0 && item < total)
                atomicAdd(&scm[s * COUT + co], val);
        }
    }

    if (EPI) {
        __syncthreads();
        if (t < SPB) {
            int s = t;
            float dot = 0.f, ssum = 0.f;
            const float inv = 1.f / (float)(PH * PW);
            for (int c = 0; c < COUT; c++) {
                float cm = scm[s * COUT + c] * inv;
                dot  += cm * asum_next[c];
                ssum += cm * cm;
            }
            float v = dot / (sqrtf(25.f * ssum) + EPSF) + 0.5f * tail_next[0] + c_next[0];
            long long f = (long long)floorf(v / R_HASH);
            qh_next[b0 + s] = (int)(((f % 2) + 2) % 2);
        }
    }
}

// ---------------------------------------------------------------------------
// FC with layer-3 mask applied on load
// ---------------------------------------------------------------------------
__global__ __launch_bounds__(256)
void fc_kernel(const float* __restrict__ h, const float* __restrict__ Wo,
               const float* __restrict__ bo, float* __restrict__ out,
               const int* __restrict__ kh3, const int* __restrict__ qh3)
{
    __shared__ float sW[3200];
    __shared__ float sb[10];
    __shared__ int skh[20];
    int t = threadIdx.x;
    for (int i = t; i < 3200; i += 256) sW[i] = Wo[i];
    if (t < 10) sb[t] = bo[t];
    if (t < 20) skh[t] = kh3[t];
    __syncthreads();
    int warp = t / 32, lane = t % 32;
    int b = blockIdx.x * 8 + warp;
    int qv = qh3[b];
    const float* hb = h + (size_t)b * 320;
    float x[10];
    #pragma unroll
    for (int j = 0; j < 10; j++) {
        int idx = lane + j * 32;
        x[j] = (skh[idx >> 4] == qv) ? hb[idx] : 0.f;
    }
    #pragma unroll
    for (int o = 0; o < 10; o++) {
        float p = 0.f;
        #pragma unroll
        for (int j = 0; j < 10; j++) p += x[j] * sW[o * 320 + lane + j * 32];
        #pragma unroll
        for (int off = 16; off; off >>= 1) p += __shfl_xor_sync(0xffffffffu, p, off);
        if (lane == 0) out[b * 10 + o] = p + sb[o];
    }
}

// ---------------------------------------------------------------------------
static inline int smem_bytes(int CIN, int COUT, int SPB, int HP, int WPAD)
{
    int fl = SPB * CIN * HP * WPAD + SPB * COUT;
    int it = SPB + (SPB + 1) + SPB * COUT + SPB + SPB * CIN + (SPB + 1);
    return 4 * (fl + it);
}

extern "C" void kernel_launch(void* const* d_in, const int* in_sizes, int n_in,
                              void* d_out, int out_size)
{
    const float* x  = (const float*)d_in[0];
    const float* W1 = (const float*)d_in[1];
    const float* b1 = (const float*)d_in[2];
    const float* a1 = (const float*)d_in[3];
    const float* c1 = (const float*)d_in[4];
    const float* W2 = (const float*)d_in[5];
    const float* b2 = (const float*)d_in[6];
    const float* a2 = (const float*)d_in[7];
    const float* c2 = (const float*)d_in[8];
    const float* W3 = (const float*)d_in[9];
    const float* b3 = (const float*)d_in[10];
    const float* a3 = (const float*)d_in[11];
    const float* c3 = (const float*)d_in[12];
    const float* Wo = (const float*)d_in[13];
    const float* bo = (const float*)d_in[14];
    float* out = (float*)d_out;

    float *h1, *h2, *h3, *aux, *w1p, *w2p, *w3p; int *qh, *kh;
    cudaGetSymbolAddress((void**)&h1, g_h1);
    cudaGetSymbolAddress((void**)&h2, g_h2);
    cudaGetSymbolAddress((void**)&h3, g_h3);
    cudaGetSymbolAddress((void**)&qh, g_qh);
    cudaGetSymbolAddress((void**)&kh, g_kh);
    cudaGetSymbolAddress((void**)&aux, g_aux);
    cudaGetSymbolAddress((void**)&w1p, g_w1p);
    cudaGetSymbolAddress((void**)&w2p, g_w2p);
    cudaGetSymbolAddress((void**)&w3p, g_w3p);

    const int sm1 = smem_bytes(3, 16, 1, 36, 36);
    const int sm2 = smem_bytes(16, 20, 1, 20, 24);
    const int sm3 = smem_bytes(20, 20, 4, 12, 12);

    cudaFuncSetAttribute((const void*)conv_fused<3, 16, 32, 32, 36, 1, 128, 5, true>,
                         cudaFuncAttributeMaxDynamicSharedMemorySize, sm1);
    cudaFuncSetAttribute((const void*)conv_fused<16, 20, 16, 16, 24, 1, 128, 5, true>,
                         cudaFuncAttributeMaxDynamicSharedMemorySize, sm2);
    cudaFuncSetAttribute((const void*)conv_fused<20, 20, 8, 8, 12, 4, 128, 4, false>,
                         cudaFuncAttributeMaxDynamicSharedMemorySize, sm3);

    prep_wpad<<<32, 256>>>(W1, W2, W3);
    kh_kernel<<<1, 192>>>(W1, a1, c1, W2, a2, c2, W3, a3, c3);
    qh1_kernel<<<BATCH / 8, 256>>>(x, c1, qh);

    conv_fused<3, 16, 32, 32, 36, 1, 128, 5, true><<<BATCH, 128, sm1>>>(
        x, h1, w1p, b1, kh, qh, nullptr, nullptr,
        aux + 0, aux + 36, c2, qh + BATCH);

    conv_fused<16, 20, 16, 16, 24, 1, 128, 5, true><<<BATCH, 128, sm2>>>(
        h1, h2, w2p, b2, kh + 32, qh + BATCH, kh, qh,
        aux + 16, aux + 37, c3, qh + 2 * BATCH);

    conv_fused<20, 20, 8, 8, 12, 4, 128, 4, false><<<BATCH / 4, 128, sm3>>>(
        h2, h3, w3p, b3, kh + 64, qh + 2 * BATCH, kh + 32, qh + BATCH,
        nullptr, nullptr, nullptr, nullptr);

    fc_kernel<<<BATCH / 8, 256>>>(h3, Wo, bo, out, kh + 64, qh + 2 * BATCH);
}

// round 7
// speedup vs baseline: 1.0949x; 1.0949x over previous
#include <cuda_runtime.h>
#include <math.h>

#define R_HASH 0.2f
#define EPSF   1e-12f
#define BATCH  4096

// scratch (device globals: sanctioned scratch mechanism)
__device__ float g_h1[BATCH * 16 * 16 * 16];
__device__ float g_h2[BATCH * 20 * 8 * 8];
__device__ float g_h3[BATCH * 20 * 4 * 4];
__device__ int   g_qh[3 * BATCH];
__device__ int   g_kh[96];
__device__ float g_aux[48];
__device__ float g_w1p[16 * 3 * 28];    // padded weights, stride 28 (7xfloat4)
__device__ float g_w2p[20 * 16 * 28];
__device__ float g_w3p[20 * 20 * 28];

// ---------------------------------------------------------------------------
// Pad weights to 28-stride (16B-aligned rows for float4 loads)
// ---------------------------------------------------------------------------
__global__ void prep_wpad(const float* __restrict__ W1,
                          const float* __restrict__ W2,
                          const float* __restrict__ W3)
{
    int t = blockIdx.x * blockDim.x + threadIdx.x;
    int stride = gridDim.x * blockDim.x;
    for (int i = t; i < 48 * 28; i += stride) {
        int f = i / 28, k = i % 28;
        g_w1p[i] = (k < 25) ? W1[f * 25 + k] : 0.f;
    }
    for (int i = t; i < 320 * 28; i += stride) {
        int f = i / 28, k = i % 28;
        g_w2p[i] = (k < 25) ? W2[f * 25 + k] : 0.f;
    }
    for (int i = t; i < 400 * 28; i += stride) {
        int f = i / 28, k = i % 28;
        g_w3p[i] = (k < 25) ? W3[f * 25 + k] : 0.f;
    }
}

// ---------------------------------------------------------------------------
// Filter hashes (one warp per layer)
// ---------------------------------------------------------------------------
__device__ __forceinline__ void kh_layer(const float* W, const float* a,
                                         const float* c, int Cout, int d,
                                         int* kh_out, int t)
{
    float nrm = 0.f;
    if (t < Cout) {
        for (int j = 0; j < d; j++) { float v = W[t * d + j]; nrm += v * v; }
        nrm = sqrtf(nrm);
    }
    float mx = nrm;
    #pragma unroll
    for (int off = 16; off; off >>= 1)
        mx = fmaxf(mx, __shfl_xor_sync(0xffffffffu, mx, off));
    float scale = 1.f / (mx + EPSF);
    if (t < Cout) {
        float dot = 0.f, ss = 0.f;
        for (int j = 0; j < d; j++) {
            float v = W[t * d + j] * scale;
            dot += v * a[j];
            ss  += v * v;
        }
        float n = sqrtf(ss);
        float p = n;
        #pragma unroll
        for (int m = 0; m < 5; m++) { p = p * p; dot += p * a[d + m]; }
        dot += c[0];
        long long f = (long long)floorf(dot / R_HASH);
        kh_out[t] = (int)(((f % 2) + 2) % 2);
    }
}

__global__ void kh_kernel(const float* W1, const float* a1, const float* c1,
                          const float* W2, const float* a2, const float* c2,
                          const float* W3, const float* a3, const float* c3)
{
    int warp = threadIdx.x >> 5, t = threadIdx.x & 31;
    if (warp == 0) kh_layer(W1, a1, c1, 16, 3 * 25,  g_kh + 0,  t);
    if (warp == 1) kh_layer(W2, a2, c2, 20, 16 * 25, g_kh + 32, t);
    if (warp == 2) kh_layer(W3, a3, c3, 20, 20 * 25, g_kh + 64, t);
    if (warp == 3 && t < 16) {
        float s = 0.f; for (int j = 0; j < 25; j++) s += a2[t * 25 + j];
        g_aux[t] = s;
    }
    if (warp == 4 && t < 20) {
        float s = 0.f; for (int j = 0; j < 25; j++) s += a3[t * 25 + j];
        g_aux[16 + t] = s;
    }
    if (warp == 5) {
        if (t < 3) {
            float s = 0.f; for (int j = 0; j < 25; j++) s += a1[t * 25 + j];
            g_aux[38 + t] = s;
        }
        if (t == 3) { float s = 0.f; for (int m = 0; m < 5; m++) s += a2[400 + m]; g_aux[36] = s; }
        if (t == 4) { float s = 0.f; for (int m = 0; m < 5; m++) s += a3[500 + m]; g_aux[37] = s; }
        if (t == 5) { float s = 0.f; for (int m = 0; m < 5; m++) s += a1[75 + m];  g_aux[41] = s; }
    }
}

// ---------------------------------------------------------------------------
// Layer-1 query hash: one warp per sample
// ---------------------------------------------------------------------------
__global__ __launch_bounds__(256)
void qh1_kernel(const float* __restrict__ x, const float* __restrict__ c1,
                int* __restrict__ qh_out)
{
    int warp = threadIdx.x >> 5, lane = threadIdx.x & 31;
    int b = blockIdx.x * 8 + warp;
    const float4* xb = (const float4*)(x + (size_t)b * 3072);
    float s[3];
    #pragma unroll
    for (int c = 0; c < 3; c++) {
        float p = 0.f;
        #pragma unroll
        for (int i = lane; i < 256; i += 32) {
            float4 v = xb[c * 256 + i];
            p += (v.x + v.y) + (v.z + v.w);
        }
        #pragma unroll
        for (int off = 16; off; off >>= 1)
            p += __shfl_xor_sync(0xffffffffu, p, off);
        s[c] = p;
    }
    if (lane == 0) {
        float dot = 0.f, ss = 0.f;
        #pragma unroll
        for (int c = 0; c < 3; c++) {
            float cm = s[c] * (1.f / 1024.f);
            dot += cm * g_aux[38 + c];
            ss  += cm * cm;
        }
        float v = dot / (sqrtf(25.f * ss) + EPSF) + 0.5f * g_aux[41] + c1[0];
        long long f = (long long)floorf(v / R_HASH);
        qh_out[b] = (int)(((f % 2) + 2) % 2);
    }
}

// ---------------------------------------------------------------------------
// Fused conv5x5(pad2)+bias+relu+mask+maxpool2.
// Compacted active-channel x tiles in smem; padded weights via 7x float4 __ldg.
// Optional fused next-layer query-hash epilogue.
// ---------------------------------------------------------------------------
template <int CIN, int COUT, int H, int W, int WPAD, int SPB, int T, int MINB, bool EPI>
__global__ __launch_bounds__(T, MINB)
void conv_fused(const float* __restrict__ in, float* __restrict__ out,
                const float* __restrict__ wpad, const float* __restrict__ bias,
                const int* __restrict__ kh, const int* __restrict__ qh,
                const int* __restrict__ kh_prev, const int* __restrict__ qh_prev,
                const float* __restrict__ asum_next,
                const float* __restrict__ tail_next,
                const float* __restrict__ c_next, int* __restrict__ qh_next)
{
    constexpr int HP = H + 4;
    constexpr int PH = H / 2, PW = W / 2, PX2 = PW / 2;
    constexpr int PP = PH * PX2;                  // items per (sample, co)
    constexpr int SEG = (PP < 32) ? PP : 32;
    constexpr int CHW = HP * WPAD;

    extern __shared__ float sm[];
    float* sx  = sm;                              // SPB*CIN*CHW (worst case)
    float* scm = sx + SPB * CIN * CHW;            // SPB*COUT
    int* nact  = (int*)(scm + SPB * COUT);        // SPB
    int* soff  = nact + SPB;                      // SPB+1
    int* actco = soff + SPB + 1;                  // SPB*COUT
    int* nci   = actco + SPB * COUT;              // SPB
    int* actci = nci + SPB;                       // SPB*CIN
    int* sxoff = actci + SPB * CIN;               // SPB+1

    const int b0 = blockIdx.x * SPB;
    const int t  = threadIdx.x;

    if (t < SPB) {
        int s = t, n = 0, qv = qh[b0 + s];
        for (int co = 0; co < COUT; co++)
            if (kh[co] == qv) actco[s * COUT + n++] = co;
        nact[s] = n;
    } else if (t >= 32 && t < 32 + SPB) {
        int s = t - 32, n = 0;
        if (kh_prev) {
            int qv = qh_prev[b0 + s];
            for (int c = 0; c < CIN; c++)
                if (kh_prev[c] == qv) actci[s * CIN + n++] = c;
        } else {
            for (int c = 0; c < CIN; c++) actci[s * CIN + n++] = c;
        }
        nci[s] = n;
    }
    if (EPI) for (int i = t; i < SPB * COUT; i += T) scm[i] = 0.f;
    __syncthreads();
    if (t == 0) {
        int o = 0, xo = 0;
        for (int s = 0; s < SPB; s++) {
            soff[s] = o;  o  += nact[s] * PP;
            sxoff[s] = xo; xo += nci[s];
        }
        soff[SPB] = o; sxoff[SPB] = xo;
    }
    __syncthreads();

    // stage compacted active-channel input tiles
    const int total_ch = sxoff[SPB];
    for (int i = t; i < total_ch * CHW; i += T) {
        int pos = i % CHW, ch = i / CHW;
        int s = 0;
        #pragma unroll
        for (int ss = 0; ss < SPB - 1; ss++)
            if (ch >= sxoff[ss + 1]) s = ss + 1;
        int c = actci[s * CIN + (ch - sxoff[s])];
        int py = pos / WPAD, px = pos % WPAD;
        int y = py - 2, x = px - 2;
        float v = 0.f;
        if ((unsigned)y < (unsigned)H && (unsigned)x < (unsigned)W)
            v = in[((size_t)(b0 + s) * CIN + c) * (H * W) + y * W + x];
        sx[i] = v;
    }
    __syncthreads();
    const int total = soff[SPB];

    for (int item = t;; item += T) {
        if (!__ballot_sync(0xffffffffu, item < total)) break;
        float val = 0.f;
        int s = 0, co = 0;
        if (item < total) {
            #pragma unroll
            for (int ss = 0; ss < SPB - 1; ss++)
                if (item >= soff[ss + 1]) s = ss + 1;
            int local = item - soff[s];
            co = actco[s * COUT + local / PP];
            int rr = local % PP;
            int py = rr / PX2, px2 = rr % PX2;

            float acc[2][4] = {};
            const float* xb = sx + (size_t)sxoff[s] * CHW + (2 * py) * WPAD + 4 * px2;
            const int n_ci = nci[s];
            const int* ci = actci + s * CIN;
            const float* wb_ = wpad + (size_t)co * CIN * 28;

            for (int j = 0; j < n_ci; j++) {
                const float4* wr = (const float4*)(wb_ + ci[j] * 28);
                float4 q0 = __ldg(wr + 0), q1 = __ldg(wr + 1), q2 = __ldg(wr + 2);
                float4 q3 = __ldg(wr + 3), q4 = __ldg(wr + 4), q5 = __ldg(wr + 5);
                float4 q6 = __ldg(wr + 6);
                float w[25] = {q0.x, q0.y, q0.z, q0.w, q1.x, q1.y, q1.z, q1.w,
                               q2.x, q2.y, q2.z, q2.w, q3.x, q3.y, q3.z, q3.w,
                               q4.x, q4.y, q4.z, q4.w, q5.x, q5.y, q5.z, q5.w,
                               q6.x};
                const float* xs = xb + j * CHW;
                #pragma unroll
                for (int rw = 0; rw < 6; rw++) {
                    float4 x0 = *(const float4*)(xs + rw * WPAD);
                    float4 x1 = *(const float4*)(xs + rw * WPAD + 4);
                    float xr[8] = {x0.x, x0.y, x0.z, x0.w, x1.x, x1.y, x1.z, x1.w};
                    if (rw < 5) {
                        #pragma unroll
                        for (int kx = 0; kx < 5; kx++) {
                            float wa = w[rw * 5 + kx];
                            acc[0][0] += xr[kx + 0] * wa;
                            acc[0][1] += xr[kx + 1] * wa;
                            acc[0][2] += xr[kx + 2] * wa;
                            acc[0][3] += xr[kx + 3] * wa;
                        }
                    }
                    if (rw > 0) {
                        #pragma unroll
                        for (int kx = 0; kx < 5; kx++) {
                            float wb = w[(rw - 1) * 5 + kx];
                            acc[1][0] += xr[kx + 0] * wb;
                            acc[1][1] += xr[kx + 1] * wb;
                            acc[1][2] += xr[kx + 2] * wb;
                            acc[1][3] += xr[kx + 3] * wb;
                        }
                    }
                }
            }
            float bv = __ldg(bias + co);
            float v00 = fmaxf(acc[0][0] + bv, 0.f), v01 = fmaxf(acc[0][1] + bv, 0.f);
            float v02 = fmaxf(acc[0][2] + bv, 0.f), v03 = fmaxf(acc[0][3] + bv, 0.f);
            float v10 = fmaxf(acc[1][0] + bv, 0.f), v11 = fmaxf(acc[1][1] + bv, 0.f);
            float v12 = fmaxf(acc[1][2] + bv, 0.f), v13 = fmaxf(acc[1][3] + bv, 0.f);
            float o0 = fmaxf(fmaxf(v00, v01), fmaxf(v10, v11));
            float o1 = fmaxf(fmaxf(v02, v03), fmaxf(v12, v13));
            float2* op = (float2*)&out[(((size_t)(b0 + s) * COUT + co) * PH + py) * PW + px2 * 2];
            *op = make_float2(o0, o1);
            val = o0 + o1;
        }
        if (EPI) {
            #pragma unroll
            for (int off = SEG / 2; off; off >>= 1)
                val += __shfl_xor_sync(0xffffffffu, val, off);
            if ((t & (SEG - 1)) == 0 && item < total)
                atomicAdd(&scm[s * COUT + co], val);
        }
    }

    if (EPI) {
        __syncthreads();
        if (t < SPB) {
            int s = t;
            float dot = 0.f, ssum = 0.f;
            const float inv = 1.f / (float)(PH * PW);
            for (int c = 0; c < COUT; c++) {
                float cm = scm[s * COUT + c] * inv;
                dot  += cm * asum_next[c];
                ssum += cm * cm;
            }
            float v = dot / (sqrtf(25.f * ssum) + EPSF) + 0.5f * tail_next[0] + c_next[0];
            long long f = (long long)floorf(v / R_HASH);
            qh_next[b0 + s] = (int)(((f % 2) + 2) % 2);
        }
    }
}

// ---------------------------------------------------------------------------
// FC with layer-3 mask applied on load
// ---------------------------------------------------------------------------
__global__ __launch_bounds__(256)
void fc_kernel(const float* __restrict__ h, const float* __restrict__ Wo,
               const float* __restrict__ bo, float* __restrict__ out,
               const int* __restrict__ kh3, const int* __restrict__ qh3)
{
    __shared__ float sW[3200];
    __shared__ float sb[10];
    __shared__ int skh[20];
    int t = threadIdx.x;
    for (int i = t; i < 3200; i += 256) sW[i] = Wo[i];
    if (t < 10) sb[t] = bo[t];
    if (t < 20) skh[t] = kh3[t];
    __syncthreads();
    int warp = t / 32, lane = t % 32;
    int b = blockIdx.x * 8 + warp;
    int qv = qh3[b];
    const float* hb = h + (size_t)b * 320;
    float x[10];
    #pragma unroll
    for (int j = 0; j < 10; j++) {
        int idx = lane + j * 32;
        x[j] = (skh[idx >> 4] == qv) ? hb[idx] : 0.f;
    }
    #pragma unroll
    for (int o = 0; o < 10; o++) {
        float p = 0.f;
        #pragma unroll
        for (int j = 0; j < 10; j++) p += x[j] * sW[o * 320 + lane + j * 32];
        #pragma unroll
        for (int off = 16; off; off >>= 1) p += __shfl_xor_sync(0xffffffffu, p, off);
        if (lane == 0) out[b * 10 + o] = p + sb[o];
    }
}

// ---------------------------------------------------------------------------
static inline int smem_bytes(int CIN, int COUT, int SPB, int HP, int WPAD)
{
    int fl = SPB * CIN * HP * WPAD + SPB * COUT;
    int it = SPB + (SPB + 1) + SPB * COUT + SPB + SPB * CIN + (SPB + 1);
    return 4 * (fl + it);
}

extern "C" void kernel_launch(void* const* d_in, const int* in_sizes, int n_in,
                              void* d_out, int out_size)
{
    const float* x  = (const float*)d_in[0];
    const float* W1 = (const float*)d_in[1];
    const float* b1 = (const float*)d_in[2];
    const float* a1 = (const float*)d_in[3];
    const float* c1 = (const float*)d_in[4];
    const float* W2 = (const float*)d_in[5];
    const float* b2 = (const float*)d_in[6];
    const float* a2 = (const float*)d_in[7];
    const float* c2 = (const float*)d_in[8];
    const float* W3 = (const float*)d_in[9];
    const float* b3 = (const float*)d_in[10];
    const float* a3 = (const float*)d_in[11];
    const float* c3 = (const float*)d_in[12];
    const float* Wo = (const float*)d_in[13];
    const float* bo = (const float*)d_in[14];
    float* out = (float*)d_out;

    float *h1, *h2, *h3, *aux, *w1p, *w2p, *w3p; int *qh, *kh;
    cudaGetSymbolAddress((void**)&h1, g_h1);
    cudaGetSymbolAddress((void**)&h2, g_h2);
    cudaGetSymbolAddress((void**)&h3, g_h3);
    cudaGetSymbolAddress((void**)&qh, g_qh);
    cudaGetSymbolAddress((void**)&kh, g_kh);
    cudaGetSymbolAddress((void**)&aux, g_aux);
    cudaGetSymbolAddress((void**)&w1p, g_w1p);
    cudaGetSymbolAddress((void**)&w2p, g_w2p);
    cudaGetSymbolAddress((void**)&w3p, g_w3p);

    const int sm1 = smem_bytes(3, 16, 1, 36, 36);
    const int sm2 = smem_bytes(16, 20, 2, 20, 24);
    const int sm3 = smem_bytes(20, 20, 2, 12, 12);

    cudaFuncSetAttribute((const void*)conv_fused<3, 16, 32, 32, 36, 1, 256, 4, true>,
                         cudaFuncAttributeMaxDynamicSharedMemorySize, sm1);
    cudaFuncSetAttribute((const void*)conv_fused<16, 20, 16, 16, 24, 2, 256, 4, true>,
                         cudaFuncAttributeMaxDynamicSharedMemorySize, sm2);
    cudaFuncSetAttribute((const void*)conv_fused<20, 20, 8, 8, 12, 2, 128, 8, false>,
                         cudaFuncAttributeMaxDynamicSharedMemorySize, sm3);

    prep_wpad<<<32, 256>>>(W1, W2, W3);
    kh_kernel<<<1, 192>>>(W1, a1, c1, W2, a2, c2, W3, a3, c3);
    qh1_kernel<<<BATCH / 8, 256>>>(x, c1, qh);

    conv_fused<3, 16, 32, 32, 36, 1, 256, 4, true><<<BATCH, 256, sm1>>>(
        x, h1, w1p, b1, kh, qh, nullptr, nullptr,
        aux + 0, aux + 36, c2, qh + BATCH);

    conv_fused<16, 20, 16, 16, 24, 2, 256, 4, true><<<BATCH / 2, 256, sm2>>>(
        h1, h2, w2p, b2, kh + 32, qh + BATCH, kh, qh,
        aux + 16, aux + 37, c3, qh + 2 * BATCH);

    conv_fused<20, 20, 8, 8, 12, 2, 128, 8, false><<<BATCH / 2, 128, sm3>>>(
        h2, h3, w3p, b3, kh + 64, qh + 2 * BATCH, kh + 32, qh + BATCH,
        nullptr, nullptr, nullptr, nullptr);

    fc_kernel<<<BATCH / 8, 256>>>(h3, Wo, bo, out, kh + 64, qh + 2 * BATCH);
}